// round 14
// baseline (speedup 1.0000x reference)
#include <cuda_runtime.h>
#include <cuda_bf16.h>
#include <math.h>
#include <stdint.h>

#define DIM   192
#define HEADS 6
#define HD    32
#define NWIN  1024          // 4 * 16 * 16
#define NQTOK 65536         // 1024 * 64  (== B*L)
#define NKVTOK 262144       // 1024 * 256
#define SCALE 0.17677669529663687f   // 32^-0.5

// ---------------- scratch (device globals; no runtime allocation) ----------------
__device__ __nv_bfloat16 g_x2w[(size_t)NKVTOK * DIM];     // x2 bf16, WINDOW order
__device__ __nv_bfloat16 g_xn [(size_t)NQTOK * DIM];      // LN1 out, window order
__device__ __nv_bfloat16 g_q  [(size_t)NQTOK * DIM];      // q projection
__device__ __nv_bfloat16 g_kv [(size_t)NKVTOK * 2 * DIM]; // k | v, window order
__device__ __nv_bfloat16 g_ao [(size_t)NQTOK * DIM];      // attention output
__device__ float         g_x1 [(size_t)NQTOK * DIM];      // x after first residual (fp32)
__device__ __nv_bfloat16 g_ln2[(size_t)NQTOK * DIM];      // LN2 output
__device__ __nv_bfloat16 g_h  [(size_t)NQTOK * 4 * DIM];  // gelu(fc1) output
// bf16 weights (pre-converted once per launch)
__device__ __nv_bfloat16 g_wq [192 * 192];
__device__ __nv_bfloat16 g_wkv[384 * 192];
__device__ __nv_bfloat16 g_wp [192 * 192];
__device__ __nv_bfloat16 g_w1 [768 * 192];
__device__ __nv_bfloat16 g_w2 [192 * 768];

// ---------------- helpers ----------------
__device__ __forceinline__ void mma_bf16(float* d, const uint32_t* a, const uint32_t* b) {
    asm volatile(
        "mma.sync.aligned.m16n8k16.row.col.f32.bf16.bf16.f32 "
        "{%0,%1,%2,%3}, {%4,%5,%6,%7}, {%8,%9}, {%0,%1,%2,%3};\n"
        : "+f"(d[0]), "+f"(d[1]), "+f"(d[2]), "+f"(d[3])
        : "r"(a[0]), "r"(a[1]), "r"(a[2]), "r"(a[3]),
          "r"(b[0]), "r"(b[1]));
}
// pack: lo half = x (first k), hi half = y
__device__ __forceinline__ uint32_t packbf(float x, float y) {
    uint32_t r;
    asm("cvt.rn.bf16x2.f32 %0, %1, %2;" : "=r"(r) : "f"(y), "f"(x));
    return r;
}
__device__ __forceinline__ void cp16(uint32_t dst, const void* src) {
    asm volatile("cp.async.cg.shared.global [%0], [%1], 16;\n" :: "r"(dst), "l"(src));
}
#define CP_COMMIT() asm volatile("cp.async.commit_group;\n")
#define CP_WAIT1()  asm volatile("cp.async.wait_group 1;\n")
#define CP_WAIT0()  asm volatile("cp.async.wait_group 0;\n")

// ---------------- all weights fp32 -> bf16 in ONE launch ----------------
// segment sizes in float4 units: 9216, 18432, 9216, 36864, 36864 (cum 110592)
__global__ __launch_bounds__(256) void cvt_all(
    const float* __restrict__ s0, const float* __restrict__ s1,
    const float* __restrict__ s2, const float* __restrict__ s3,
    const float* __restrict__ s4)
{
    int i = blockIdx.x * 256 + threadIdx.x;
    const float* s; __nv_bfloat16* d; int base;
    if      (i <  9216) { s = s0; d = g_wq;  base = 0; }
    else if (i < 27648) { s = s1; d = g_wkv; base = 9216; }
    else if (i < 36864) { s = s2; d = g_wp;  base = 27648; }
    else if (i < 73728) { s = s3; d = g_w1;  base = 36864; }
    else                { s = s4; d = g_w2;  base = 73728; }
    int j = i - base;
    float4 v = ((const float4*)s)[j];
    uint2 o;
    o.x = packbf(v.x, v.y);
    o.y = packbf(v.z, v.w);
    ((uint2*)d)[j] = o;
}

// ---------------- x2: fp32 natural order -> bf16 window order -------------
// warp per token: coalesced float2 reads, coalesced u32 writes.
__global__ __launch_bounds__(256) void gather_x2(const float* __restrict__ x2)
{
    int warp = threadIdx.x >> 5, lane = threadIdx.x & 31;
    int tok = blockIdx.x * 8 + warp;        // window-order token
    int win = tok >> 8, t = tok & 255;
    int bb = win >> 8, wi = win & 255;
    int wr = wi >> 4,  wc = wi & 15;
    int rr = t  >> 4,  cc = t  & 15;
    int nat = bb * 65536 + (wr * 16 + rr) * 256 + wc * 16 + cc;
    const float* src = x2 + (size_t)nat * DIM;
    uint32_t* dst = (uint32_t*)g_x2w + (size_t)tok * (DIM / 2);
    #pragma unroll
    for (int j = 0; j < 3; j++) {
        float2 v = *(const float2*)(src + lane * 2 + j * 64);
        dst[lane + j * 32] = packbf(v.x, v.y);
    }
}

// ---------------- LayerNorm: warp per token, 8 tokens/block ----------------
template<int MODE>
__global__ __launch_bounds__(256) void ln_kernel(
    const float* __restrict__ x, const float* __restrict__ w,
    const float* __restrict__ b, __nv_bfloat16* __restrict__ out)
{
    int warp = threadIdx.x >> 5, lane = threadIdx.x & 31;
    int tok = blockIdx.x * 8 + warp;
    int in_row, out_row;
    if (MODE == 0) {
        int win = tok >> 6, t = tok & 63;
        int bb = win >> 8, wi = win & 255;
        int wr = wi >> 4,  wc = wi & 15;
        int r  = t  >> 3,  c  = t  & 7;
        in_row  = bb * 16384 + (wr * 8 + r) * 128 + (wc * 8 + c);
        out_row = tok;
    } else {
        in_row = out_row = tok;
    }
    const float* xr = x + (size_t)in_row * DIM;
    float v[6];
    float s1 = 0.f, s2 = 0.f;
    #pragma unroll
    for (int i = 0; i < 6; i++) {
        v[i] = xr[lane + i * 32];
        s1 += v[i]; s2 += v[i] * v[i];
    }
    #pragma unroll
    for (int off = 16; off; off >>= 1) {
        s1 += __shfl_xor_sync(0xffffffffu, s1, off);
        s2 += __shfl_xor_sync(0xffffffffu, s2, off);
    }
    float mean = s1 * (1.0f / 192.0f);
    float var  = s2 * (1.0f / 192.0f) - mean * mean;
    float rstd = rsqrtf(var + 1e-5f);
    __nv_bfloat16* orow = out + (size_t)out_row * DIM;
    #pragma unroll
    for (int i = 0; i < 6; i++) {
        int c = lane + i * 32;
        orow[c] = __float2bfloat16((v[i] - mean) * rstd * w[c] + b[c]);
    }
}

// ---------------- BF16 GEMM, BM=256, cp.async 3-stage ----------------
// C = A @ W^T + bias.  A, W bf16; W (N, K) row-major.
// GRID: x = N-blocks (fastest), y = M-blocks -> A rows stay L2-hot.
// MODE 0: plain -> bf16.
// MODE 2: + add[nat_row] -> fp32, window-reversed.  MODE 3: gelu -> bf16.
// MODE 4: + add[row] -> fp32.
#define BAS 20                          // u32 row stride, bf16 A / B tiles
#define BSZ32 (64 * BAS)
#define SM_BF ((3 * 256 * BAS + 3 * BSZ32) * 4)

template<int MODE, int N, int K>
__global__ __launch_bounds__(256) void gemm_bf16(
    const __nv_bfloat16* __restrict__ A, const __nv_bfloat16* __restrict__ W,
    const float* __restrict__ bias, void* __restrict__ Cv,
    const float* __restrict__ add)
{
    constexpr int BM = 256, BN = 64;
    constexpr int ASZ = 256 * BAS;              // 4-byte units
    constexpr int NIT = K / 32;
    extern __shared__ uint32_t smg4[];
    uint32_t* Asm = smg4;                       // 3 * ASZ
    uint32_t* Bsm = smg4 + 3 * ASZ;             // 3 * BSZ32

    int tid = threadIdx.x;
    int mb = blockIdx.y * BM, nb = blockIdx.x * BN;   // x = N (fastest)
    int warp = tid >> 5, lane = tid & 31;
    int wm = warp & 3, wn = warp >> 2;         // 4m x 2n warp grid, warp = 64x32
    int g = lane >> 2, tig = lane & 3;

    int brow = tid >> 2, bchunk = tid & 3;

    uint32_t sA = (uint32_t)__cvta_generic_to_shared(Asm);
    uint32_t sB = (uint32_t)__cvta_generic_to_shared(Bsm);

    auto issue = [&](int it, int buf) {
        int k0 = it * 32;
        uint32_t da = sA + (uint32_t)(buf * ASZ) * 4u;
        #pragma unroll
        for (int p = 0; p < 4; p++) {
            int r = brow + p * 64;
            cp16(da + (uint32_t)(r * BAS + bchunk * 4) * 4u,
                 A + (size_t)(mb + r) * K + k0 + bchunk * 8);
        }
        uint32_t db = sB + (uint32_t)(buf * BSZ32) * 4u;
        cp16(db + (uint32_t)(brow * BAS + bchunk * 4) * 4u,
             W + (size_t)(nb + brow) * K + k0 + bchunk * 8);
    };

    float acc[4][4][4];
    #pragma unroll
    for (int mt = 0; mt < 4; mt++)
        #pragma unroll
        for (int nt = 0; nt < 4; nt++)
            #pragma unroll
            for (int i = 0; i < 4; i++) acc[mt][nt][i] = 0.f;

    issue(0, 0); CP_COMMIT();
    issue(1, 1); CP_COMMIT();

    for (int it = 0; it < NIT; it++) {
        int buf = it % 3;
        if (it + 1 < NIT) CP_WAIT1(); else CP_WAIT0();
        __syncthreads();

        const uint32_t* as4 = Asm + buf * ASZ;
        const uint32_t* bs4 = Bsm + buf * BSZ32;
        #pragma unroll
        for (int ks = 0; ks < 2; ks++) {
            uint32_t a[4][4], b[4][2];
            #pragma unroll
            for (int mt = 0; mt < 4; mt++) {
                int r0 = wm * 64 + mt * 16;
                const uint32_t* pr = as4 + (r0 + g) * BAS + 8 * ks + tig;
                a[mt][0] = pr[0];
                a[mt][1] = pr[8 * BAS];
                a[mt][2] = pr[4];
                a[mt][3] = pr[8 * BAS + 4];
            }
            #pragma unroll
            for (int nt = 0; nt < 4; nt++) {
                const uint32_t* pc = bs4 + (wn * 32 + nt * 8 + g) * BAS + 8 * ks + tig;
                b[nt][0] = pc[0];
                b[nt][1] = pc[4];
            }
            #pragma unroll
            for (int mt = 0; mt < 4; mt++)
                #pragma unroll
                for (int nt = 0; nt < 4; nt++)
                    mma_bf16(acc[mt][nt], a[mt], b[nt]);
        }
        __syncthreads();
        if (it + 2 < NIT) { issue(it + 2, (it + 2) % 3); CP_COMMIT(); }
    }

    #pragma unroll
    for (int mt = 0; mt < 4; mt++) {
        #pragma unroll
        for (int half = 0; half < 2; half++) {
            int row = mb + wm * 64 + mt * 16 + g + half * 8;
            int nat = row;
            if (MODE == 2) {
                int win = row >> 6, t = row & 63;
                int bI = win >> 8, wi = win & 255;
                int wr = wi >> 4,  wc = wi & 15;
                int rr = t  >> 3,  cc = t  & 7;
                nat = bI * 16384 + (wr * 8 + rr) * 128 + (wc * 8 + cc);
            }
            #pragma unroll
            for (int nt = 0; nt < 4; nt++) {
                int col = nb + wn * 32 + nt * 8 + tig * 2;
                float ox = acc[mt][nt][half * 2 + 0] + bias[col];
                float oy = acc[mt][nt][half * 2 + 1] + bias[col + 1];
                if (MODE == 2) {
                    float* C = (float*)Cv;
                    float2 s = *(const float2*)(add + (size_t)nat * DIM + col);
                    *(float2*)(C + (size_t)nat * DIM + col) = make_float2(ox + s.x, oy + s.y);
                } else if (MODE == 4) {
                    float* C = (float*)Cv;
                    float2 s = *(const float2*)(add + (size_t)row * N + col);
                    *(float2*)(C + (size_t)row * N + col) = make_float2(ox + s.x, oy + s.y);
                } else {
                    if (MODE == 3) {
                        ox = 0.5f * ox * (1.0f + erff(ox * 0.70710678118654752f));
                        oy = 0.5f * oy * (1.0f + erff(oy * 0.70710678118654752f));
                    }
                    __nv_bfloat16* C = (__nv_bfloat16*)Cv;
                    *(uint32_t*)(C + (size_t)row * N + col) = packbf(ox, oy);
                }
            }
        }
    }
}

// ---------------- Attention v4: all-bf16 fragments, shuffle-free PV -----------
// 128 threads = 4 warps per (window, head). Warp w owns q-rows 16w..16w+15 and
// all 256 KV. S (16x256) in fp32 accumulators; P->A-fragment is a pure pack
// (accumulator col layout {2t,2t+1} == bf16 A-fragment layout). No shuffles.
#define AQS 20      // u32 row stride for Q/K (16 data + 4 pad)
#define AVS 132     // u32 row stride for VT (128 data + 4 pad)
#define OFFK  1280
#define OFFVT 6400
#define OFFB  10624
#define ATTN_SMEM_BYTES ((10624 + 532) * 4)

__global__ __launch_bounds__(128) void attn_kernel(const float* __restrict__ rel_bias)
{
    extern __shared__ uint32_t sm4[];
    uint32_t* sQp  = sm4;            // 64 x 20
    uint32_t* sKp  = sm4 + OFFK;     // 256 x 20
    uint32_t* sVTp = sm4 + OFFVT;    // 32 x 132 : VT[d][j2] = {V[2j2][d], V[2j2+1][d]}
    float*    sB   = (float*)(sm4 + OFFB);   // 529

    int win = blockIdx.x, h = blockIdx.y;
    int tid = threadIdx.x;

    for (int r = tid; r < 529; r += 128) sB[r] = rel_bias[r * HEADS + h];

    const __nv_bfloat16* qb = g_q + (size_t)win * 64 * DIM + h * HD;
    #pragma unroll
    for (int it = 0; it < 2; it++) {
        int id = tid + it * 128;               // 0..255
        int row = id >> 2, c = id & 3;
        uint4 v = *(const uint4*)(qb + (size_t)row * DIM + c * 8);
        *(uint4*)&sQp[row * AQS + c * 4] = v;
    }
    const __nv_bfloat16* kb = g_kv + (size_t)win * 256 * (2 * DIM) + h * HD;
    const __nv_bfloat16* vb = kb + DIM;
    #pragma unroll
    for (int it = 0; it < 8; it++) {
        int id = tid + it * 128;               // 0..1023
        int row = id >> 2, c = id & 3;
        uint4 v = *(const uint4*)(kb + (size_t)row * (2 * DIM) + c * 8);
        *(uint4*)&sKp[row * AQS + c * 4] = v;
    }
    // V: thread = j2 (0..127), c = d-chunk
    #pragma unroll
    for (int c = 0; c < 4; c++) {
        int j2 = tid;
        uint4 r0 = *(const uint4*)(vb + (size_t)(2 * j2) * (2 * DIM) + c * 8);
        uint4 r1 = *(const uint4*)(vb + (size_t)(2 * j2 + 1) * (2 * DIM) + c * 8);
        const uint32_t* x = (const uint32_t*)&r0;
        const uint32_t* y = (const uint32_t*)&r1;
        #pragma unroll
        for (int dd = 0; dd < 4; dd++) {
            sVTp[(c * 8 + 2 * dd + 0) * AVS + j2] = __byte_perm(x[dd], y[dd], 0x5410);
            sVTp[(c * 8 + 2 * dd + 1) * AVS + j2] = __byte_perm(x[dd], y[dd], 0x7632);
        }
    }
    __syncthreads();

    int warp = tid >> 5, lane = tid & 31;
    int g = lane >> 2, tig = lane & 3;
    int r0 = warp * 16;

    // ---- QK: S = Q @ K^T (two k16 steps), 16x256 in registers
    float acc[32][4];
    #pragma unroll
    for (int nt = 0; nt < 32; nt++)
        #pragma unroll
        for (int i = 0; i < 4; i++) acc[nt][i] = 0.f;

    #pragma unroll
    for (int ks = 0; ks < 2; ks++) {
        const uint32_t* pq = sQp + (r0 + g) * AQS + 8 * ks + tig;
        uint32_t a[4];
        a[0] = pq[0];
        a[1] = pq[8 * AQS];
        a[2] = pq[4];
        a[3] = pq[8 * AQS + 4];
        #pragma unroll
        for (int nt = 0; nt < 32; nt++) {
            const uint32_t* pk = sKp + (nt * 8 + g) * AQS + 8 * ks + tig;
            uint32_t b[2] = {pk[0], pk[4]};
            mma_bf16(acc[nt], a, b);
        }
    }

    // ---- scale + bias: ridx = 23*(i>>3)+(i&7)+360 - 23*(j>>4)-(j&15)
    int i_lo = r0 + g, i_hi = i_lo + 8;
    int xlo = (i_lo >> 3) * 23 + (i_lo & 7) + 360;
    int xhi = (i_hi >> 3) * 23 + (i_hi & 7) + 360;
    #pragma unroll
    for (int nt = 0; nt < 32; nt++) {
        int j0 = nt * 8 + tig * 2, j1 = j0 + 1;
        int y0 = 23 * (j0 >> 4) + (j0 & 15);
        int y1 = 23 * (j1 >> 4) + (j1 & 15);
        acc[nt][0] = acc[nt][0] * SCALE + sB[xlo - y0];
        acc[nt][1] = acc[nt][1] * SCALE + sB[xlo - y1];
        acc[nt][2] = acc[nt][2] * SCALE + sB[xhi - y0];
        acc[nt][3] = acc[nt][3] * SCALE + sB[xhi - y1];
    }

    // ---- softmax, quad-shuffle reductions only
    float mlo = -1e30f, mhi = -1e30f;
    #pragma unroll
    for (int nt = 0; nt < 32; nt++) {
        mlo = fmaxf(mlo, fmaxf(acc[nt][0], acc[nt][1]));
        mhi = fmaxf(mhi, fmaxf(acc[nt][2], acc[nt][3]));
    }
    #pragma unroll
    for (int off = 1; off < 4; off <<= 1) {
        mlo = fmaxf(mlo, __shfl_xor_sync(0xffffffffu, mlo, off));
        mhi = fmaxf(mhi, __shfl_xor_sync(0xffffffffu, mhi, off));
    }
    float slo = 0.f, shi = 0.f;
    #pragma unroll
    for (int nt = 0; nt < 32; nt++) {
        acc[nt][0] = __expf(acc[nt][0] - mlo); slo += acc[nt][0];
        acc[nt][1] = __expf(acc[nt][1] - mlo); slo += acc[nt][1];
        acc[nt][2] = __expf(acc[nt][2] - mhi); shi += acc[nt][2];
        acc[nt][3] = __expf(acc[nt][3] - mhi); shi += acc[nt][3];
    }
    #pragma unroll
    for (int off = 1; off < 4; off <<= 1) {
        slo += __shfl_xor_sync(0xffffffffu, slo, off);
        shi += __shfl_xor_sync(0xffffffffu, shi, off);
    }
    float invlo = 1.0f / slo, invhi = 1.0f / shi;
    #pragma unroll
    for (int nt = 0; nt < 32; nt++) {
        acc[nt][0] *= invlo; acc[nt][1] *= invlo;
        acc[nt][2] *= invhi; acc[nt][3] *= invhi;
    }

    // ---- PV: O = P @ V. P accumulator IS the bf16 A-fragment (pack only).
    float o[4][4];
    #pragma unroll
    for (int nt = 0; nt < 4; nt++)
        #pragma unroll
        for (int i = 0; i < 4; i++) o[nt][i] = 0.f;

    #pragma unroll
    for (int kc = 0; kc < 16; kc++) {
        uint32_t a[4];
        a[0] = packbf(acc[2 * kc][0],     acc[2 * kc][1]);
        a[1] = packbf(acc[2 * kc][2],     acc[2 * kc][3]);
        a[2] = packbf(acc[2 * kc + 1][0], acc[2 * kc + 1][1]);
        a[3] = packbf(acc[2 * kc + 1][2], acc[2 * kc + 1][3]);
        #pragma unroll
        for (int nt = 0; nt < 4; nt++) {
            const uint32_t* pv = sVTp + (nt * 8 + g) * AVS + 8 * kc + tig;
            uint32_t b[2] = {pv[0], pv[4]};
            mma_bf16(o[nt], a, b);
        }
    }

    // ---- store O (bf16)
    __nv_bfloat16* ob = g_ao + (size_t)win * 64 * DIM + h * HD;
    #pragma unroll
    for (int nt = 0; nt < 4; nt++) {
        int col = nt * 8 + tig * 2;
        *(uint32_t*)(ob + (size_t)i_lo * DIM + col) = packbf(o[nt][0], o[nt][1]);
        *(uint32_t*)(ob + (size_t)i_hi * DIM + col) = packbf(o[nt][2], o[nt][3]);
    }
}

// ---------------- launch ----------------
extern "C" void kernel_launch(void* const* d_in, const int* in_sizes, int n_in,
                              void* d_out, int out_size)
{
    const float* x     = (const float*)d_in[0];
    const float* x2    = (const float*)d_in[1];
    const float* n1w   = (const float*)d_in[2];
    const float* n1b   = (const float*)d_in[3];
    const float* qkvw  = (const float*)d_in[4];
    const float* qkvb  = (const float*)d_in[5];
    const float* qkv2w = (const float*)d_in[6];
    const float* qkv2b = (const float*)d_in[7];
    const float* relb  = (const float*)d_in[8];
    const float* projw = (const float*)d_in[9];
    const float* projb = (const float*)d_in[10];
    const float* n2w   = (const float*)d_in[11];
    const float* n2b   = (const float*)d_in[12];
    const float* fc1w  = (const float*)d_in[13];
    const float* fc1b  = (const float*)d_in[14];
    const float* fc2w  = (const float*)d_in[15];
    const float* fc2b  = (const float*)d_in[16];
    float* out = (float*)d_out;

    __nv_bfloat16 *p_x2w, *p_xn, *p_q, *p_kv, *p_ao, *p_ln2, *p_h;
    __nv_bfloat16 *p_wq, *p_wkv, *p_wp, *p_w1, *p_w2;
    float *p_x1;
    cudaGetSymbolAddress((void**)&p_x2w, g_x2w);
    cudaGetSymbolAddress((void**)&p_xn,  g_xn);
    cudaGetSymbolAddress((void**)&p_q,   g_q);
    cudaGetSymbolAddress((void**)&p_kv,  g_kv);
    cudaGetSymbolAddress((void**)&p_ao,  g_ao);
    cudaGetSymbolAddress((void**)&p_x1,  g_x1);
    cudaGetSymbolAddress((void**)&p_ln2, g_ln2);
    cudaGetSymbolAddress((void**)&p_h,   g_h);
    cudaGetSymbolAddress((void**)&p_wq,  g_wq);
    cudaGetSymbolAddress((void**)&p_wkv, g_wkv);
    cudaGetSymbolAddress((void**)&p_wp,  g_wp);
    cudaGetSymbolAddress((void**)&p_w1,  g_w1);
    cudaGetSymbolAddress((void**)&p_w2,  g_w2);

    cudaFuncSetAttribute(attn_kernel, cudaFuncAttributeMaxDynamicSharedMemorySize, ATTN_SMEM_BYTES);
    cudaFuncSetAttribute(gemm_bf16<0, 192, 192>, cudaFuncAttributeMaxDynamicSharedMemorySize, SM_BF);
    cudaFuncSetAttribute(gemm_bf16<0, 384, 192>, cudaFuncAttributeMaxDynamicSharedMemorySize, SM_BF);
    cudaFuncSetAttribute(gemm_bf16<2, 192, 192>, cudaFuncAttributeMaxDynamicSharedMemorySize, SM_BF);
    cudaFuncSetAttribute(gemm_bf16<3, 768, 192>, cudaFuncAttributeMaxDynamicSharedMemorySize, SM_BF);
    cudaFuncSetAttribute(gemm_bf16<4, 192, 768>, cudaFuncAttributeMaxDynamicSharedMemorySize, SM_BF);

    // 0. all weights -> bf16 (one launch); x2 -> bf16 window order
    cvt_all<<<432, 256>>>(qkvw, qkv2w, projw, fc1w, fc2w);
    gather_x2<<<NKVTOK / 8, 256>>>(x2);

    // 1. LN1 + window partition (bf16 out)
    ln_kernel<0><<<NQTOK / 8, 256>>>(x, n1w, n1b, p_xn);
    // 2. q projection  (grid x = N-blocks for L2 A-reuse)
    gemm_bf16<0, 192, 192><<<dim3(3, 256), 256, SM_BF>>>(p_xn, p_wq, qkvb, p_q, nullptr);
    // 3. kv projection: plain bf16 GEMM on window-ordered x2
    gemm_bf16<0, 384, 192><<<dim3(6, 1024), 256, SM_BF>>>(p_x2w, p_wkv, qkv2b, p_kv, nullptr);
    // 4. windowed cross attention
    attn_kernel<<<dim3(NWIN, HEADS), 128, ATTN_SMEM_BYTES>>>(relb);
    // 5. output projection + shortcut + window reverse (fp32 out)
    gemm_bf16<2, 192, 192><<<dim3(3, 256), 256, SM_BF>>>(p_ao, p_wp, projb, p_x1, x);
    // 6. LN2 (bf16 out)
    ln_kernel<1><<<NQTOK / 8, 256>>>(p_x1, n2w, n2b, p_ln2);
    // 7. fc1 + gelu
    gemm_bf16<3, 768, 192><<<dim3(12, 256), 256, SM_BF>>>(p_ln2, p_w1, fc1b, p_h, nullptr);
    // 8. fc2 + residual -> output (fp32)
    gemm_bf16<4, 192, 768><<<dim3(3, 256), 256, SM_BF>>>(p_h, p_w2, fc2b, out, p_x1);
}

// round 15
// speedup vs baseline: 1.0846x; 1.0846x over previous
#include <cuda_runtime.h>
#include <cuda_bf16.h>
#include <math.h>
#include <stdint.h>

#define DIM   192
#define HEADS 6
#define HD    32
#define NWIN  1024          // 4 * 16 * 16
#define NQTOK 65536         // 1024 * 64  (== B*L)
#define NKVTOK 262144       // 1024 * 256
#define SCALE 0.17677669529663687f   // 32^-0.5

// ---------------- scratch (device globals; no runtime allocation) ----------------
__device__ __nv_bfloat16 g_xn [(size_t)NQTOK * DIM];      // LN1 out, window order
__device__ __nv_bfloat16 g_q  [(size_t)NQTOK * DIM];      // q projection
__device__ __nv_bfloat16 g_kv [(size_t)NKVTOK * 2 * DIM]; // k | v, window order
__device__ __nv_bfloat16 g_ao [(size_t)NQTOK * DIM];      // attention output
__device__ float         g_x1 [(size_t)NQTOK * DIM];      // x after first residual (fp32)
__device__ __nv_bfloat16 g_ln2[(size_t)NQTOK * DIM];      // LN2 output
__device__ __nv_bfloat16 g_h  [(size_t)NQTOK * 4 * DIM];  // gelu(fc1) output
// bf16 weights (pre-converted once per launch)
__device__ __nv_bfloat16 g_wq [192 * 192];
__device__ __nv_bfloat16 g_wkv[384 * 192];
__device__ __nv_bfloat16 g_wp [192 * 192];
__device__ __nv_bfloat16 g_w1 [768 * 192];
__device__ __nv_bfloat16 g_w2 [192 * 768];

// ---------------- helpers ----------------
__device__ __forceinline__ void mma_bf16(float* d, const uint32_t* a, const uint32_t* b) {
    asm volatile(
        "mma.sync.aligned.m16n8k16.row.col.f32.bf16.bf16.f32 "
        "{%0,%1,%2,%3}, {%4,%5,%6,%7}, {%8,%9}, {%0,%1,%2,%3};\n"
        : "+f"(d[0]), "+f"(d[1]), "+f"(d[2]), "+f"(d[3])
        : "r"(a[0]), "r"(a[1]), "r"(a[2]), "r"(a[3]),
          "r"(b[0]), "r"(b[1]));
}
// pack: lo half = x (first k), hi half = y
__device__ __forceinline__ uint32_t packbf(float x, float y) {
    uint32_t r;
    asm("cvt.rn.bf16x2.f32 %0, %1, %2;" : "=r"(r) : "f"(y), "f"(x));
    return r;
}
__device__ __forceinline__ void cp16(uint32_t dst, const void* src) {
    asm volatile("cp.async.cg.shared.global [%0], [%1], 16;\n" :: "r"(dst), "l"(src));
}
#define CP_COMMIT() asm volatile("cp.async.commit_group;\n")
#define CP_WAIT1()  asm volatile("cp.async.wait_group 1;\n")
#define CP_WAIT0()  asm volatile("cp.async.wait_group 0;\n")

// ---------------- all weights fp32 -> bf16 in ONE launch ----------------
// segment sizes in float4 units: 9216, 18432, 9216, 36864, 36864 (cum 110592)
__global__ __launch_bounds__(256) void cvt_all(
    const float* __restrict__ s0, const float* __restrict__ s1,
    const float* __restrict__ s2, const float* __restrict__ s3,
    const float* __restrict__ s4)
{
    int i = blockIdx.x * 256 + threadIdx.x;
    const float* s; __nv_bfloat16* d; int base;
    if      (i <  9216) { s = s0; d = g_wq;  base = 0; }
    else if (i < 27648) { s = s1; d = g_wkv; base = 9216; }
    else if (i < 36864) { s = s2; d = g_wp;  base = 27648; }
    else if (i < 73728) { s = s3; d = g_w1;  base = 36864; }
    else                { s = s4; d = g_w2;  base = 73728; }
    int j = i - base;
    float4 v = ((const float4*)s)[j];
    uint2 o;
    o.x = packbf(v.x, v.y);
    o.y = packbf(v.z, v.w);
    ((uint2*)d)[j] = o;
}

// ---------------- LayerNorm: warp per token, 8 tokens/block ----------------
template<int MODE>
__global__ __launch_bounds__(256) void ln_kernel(
    const float* __restrict__ x, const float* __restrict__ w,
    const float* __restrict__ b, __nv_bfloat16* __restrict__ out)
{
    int warp = threadIdx.x >> 5, lane = threadIdx.x & 31;
    int tok = blockIdx.x * 8 + warp;
    int in_row, out_row;
    if (MODE == 0) {
        int win = tok >> 6, t = tok & 63;
        int bb = win >> 8, wi = win & 255;
        int wr = wi >> 4,  wc = wi & 15;
        int r  = t  >> 3,  c  = t  & 7;
        in_row  = bb * 16384 + (wr * 8 + r) * 128 + (wc * 8 + c);
        out_row = tok;
    } else {
        in_row = out_row = tok;
    }
    const float* xr = x + (size_t)in_row * DIM;
    float v[6];
    float s1 = 0.f, s2 = 0.f;
    #pragma unroll
    for (int i = 0; i < 6; i++) {
        v[i] = xr[lane + i * 32];
        s1 += v[i]; s2 += v[i] * v[i];
    }
    #pragma unroll
    for (int off = 16; off; off >>= 1) {
        s1 += __shfl_xor_sync(0xffffffffu, s1, off);
        s2 += __shfl_xor_sync(0xffffffffu, s2, off);
    }
    float mean = s1 * (1.0f / 192.0f);
    float var  = s2 * (1.0f / 192.0f) - mean * mean;
    float rstd = rsqrtf(var + 1e-5f);
    __nv_bfloat16* orow = out + (size_t)out_row * DIM;
    #pragma unroll
    for (int i = 0; i < 6; i++) {
        int c = lane + i * 32;
        orow[c] = __float2bfloat16((v[i] - mean) * rstd * w[c] + b[c]);
    }
}

// ---------------- BF16 GEMM, templated BM, cp.async multi-stage ----------------
// C = A @ W^T + bias.  W bf16 (N, K) row-major. A bf16 (ABF, 3-stage) or
// fp32 gather (2-stage, BM=256 only).  GRID: x = N-blocks (fastest) -> A L2-hot.
// MODE 0: plain -> bf16.  MODE 1: gather x2 (fp32) through 16x16 windows -> bf16.
// MODE 2: + add[nat_row] -> fp32, window-reversed.  MODE 3: gelu -> bf16.
// MODE 4: + add[row] -> fp32.
#define BAS 20                          // u32 row stride, bf16 A / B tiles
#define FAS 40                          // float row stride, fp32 A tiles
#define BSZ32 (64 * BAS)
#define SM_BF128 ((3 * 128 * BAS + 3 * BSZ32) * 4)
#define SM_FP256 ((2 * 256 * FAS + 2 * BSZ32) * 4)

template<int MODE, int N, int K, bool ABF, int BM>
__global__ __launch_bounds__(256) void gemm_bf16(
    const void* __restrict__ Av, const __nv_bfloat16* __restrict__ W,
    const float* __restrict__ bias, void* __restrict__ Cv,
    const float* __restrict__ add)
{
    constexpr int BN = 64;
    constexpr int STAGES = ABF ? 3 : 2;
    constexpr int ASZ = ABF ? BM * BAS : BM * FAS;   // 4-byte units
    constexpr int NIT = K / 32;
    constexpr int MT = BM / 64;                      // m-subtiles per warp
    extern __shared__ uint32_t smg4[];
    uint32_t* Asm = smg4;                       // STAGES * ASZ
    uint32_t* Bsm = smg4 + STAGES * ASZ;        // STAGES * BSZ32

    int tid = threadIdx.x;
    int mb = blockIdx.y * BM, nb = blockIdx.x * BN;   // x = N (fastest)
    int warp = tid >> 5, lane = tid & 31;
    int wm = warp & 3, wn = warp >> 2;         // 4m x 2n warp grid
    int g = lane >> 2, tig = lane & 3;

    int brow = tid >> 2, bchunk = tid & 3;

    // fp32-A gather indices (MODE 1)
    int arow8 = tid >> 3, acol8 = (tid & 7) * 4;
    int asrc8[BM / 32];
    if (!ABF) {
        #pragma unroll
        for (int p = 0; p < BM / 32; p++) {
            int r = mb + arow8 + p * 32;
            int win = r >> 8, t = r & 255;
            int bb = win >> 8, wi = win & 255;
            int wr = wi >> 4,  wc = wi & 15;
            int rr = t  >> 4,  cc = t  & 15;
            asrc8[p] = bb * 65536 + (wr * 16 + rr) * 256 + (wc * 16 + cc);
        }
    }

    uint32_t sA = (uint32_t)__cvta_generic_to_shared(Asm);
    uint32_t sB = (uint32_t)__cvta_generic_to_shared(Bsm);

    auto issue = [&](int it, int buf) {
        int k0 = it * 32;
        if (ABF) {
            const __nv_bfloat16* A = (const __nv_bfloat16*)Av;
            uint32_t da = sA + (uint32_t)(buf * ASZ) * 4u;
            #pragma unroll
            for (int p = 0; p < BM / 64; p++) {
                int r = brow + p * 64;
                cp16(da + (uint32_t)(r * BAS + bchunk * 4) * 4u,
                     A + (size_t)(mb + r) * K + k0 + bchunk * 8);
            }
        } else {
            const float* A = (const float*)Av;
            uint32_t da = sA + (uint32_t)(buf * ASZ) * 4u;
            #pragma unroll
            for (int p = 0; p < BM / 32; p++)
                cp16(da + (uint32_t)((arow8 + p * 32) * FAS + acol8) * 4u,
                     A + (size_t)asrc8[p] * K + k0 + acol8);
        }
        uint32_t db = sB + (uint32_t)(buf * BSZ32) * 4u;
        cp16(db + (uint32_t)(brow * BAS + bchunk * 4) * 4u,
             W + (size_t)(nb + brow) * K + k0 + bchunk * 8);
    };

    float acc[MT][4][4];
    #pragma unroll
    for (int mt = 0; mt < MT; mt++)
        #pragma unroll
        for (int nt = 0; nt < 4; nt++)
            #pragma unroll
            for (int i = 0; i < 4; i++) acc[mt][nt][i] = 0.f;

    issue(0, 0); CP_COMMIT();
    if (STAGES == 3) { issue(1, 1); CP_COMMIT(); }

    for (int it = 0; it < NIT; it++) {
        int buf = it % STAGES;
        if (STAGES == 3) {
            if (it + 1 < NIT) CP_WAIT1(); else CP_WAIT0();
        } else {
            if (it + 1 < NIT) { issue(it + 1, (it + 1) & 1); CP_COMMIT(); CP_WAIT1(); }
            else              { CP_WAIT0(); }
        }
        __syncthreads();

        const uint32_t* as4 = Asm + buf * ASZ;
        const uint32_t* bs4 = Bsm + buf * BSZ32;
        const float* asf = (const float*)as4;
        #pragma unroll
        for (int ks = 0; ks < 2; ks++) {
            uint32_t a[MT][4], b[4][2];
            #pragma unroll
            for (int mt = 0; mt < MT; mt++) {
                int r0 = wm * (MT * 16) + mt * 16;
                if (ABF) {
                    const uint32_t* pr = as4 + (r0 + g) * BAS + 8 * ks + tig;
                    a[mt][0] = pr[0];
                    a[mt][1] = pr[8 * BAS];
                    a[mt][2] = pr[4];
                    a[mt][3] = pr[8 * BAS + 4];
                } else {
                    const float* pr = asf + (r0 + g) * FAS + 16 * ks + tig * 2;
                    float2 v0 = *(const float2*)pr;
                    float2 v1 = *(const float2*)(pr + 8 * FAS);
                    float2 v2 = *(const float2*)(pr + 8);
                    float2 v3 = *(const float2*)(pr + 8 * FAS + 8);
                    a[mt][0] = packbf(v0.x, v0.y);
                    a[mt][1] = packbf(v1.x, v1.y);
                    a[mt][2] = packbf(v2.x, v2.y);
                    a[mt][3] = packbf(v3.x, v3.y);
                }
            }
            #pragma unroll
            for (int nt = 0; nt < 4; nt++) {
                const uint32_t* pc = bs4 + (wn * 32 + nt * 8 + g) * BAS + 8 * ks + tig;
                b[nt][0] = pc[0];
                b[nt][1] = pc[4];
            }
            #pragma unroll
            for (int mt = 0; mt < MT; mt++)
                #pragma unroll
                for (int nt = 0; nt < 4; nt++)
                    mma_bf16(acc[mt][nt], a[mt], b[nt]);
        }
        __syncthreads();
        if (STAGES == 3 && it + 2 < NIT) { issue(it + 2, (it + 2) % 3); CP_COMMIT(); }
    }

    #pragma unroll
    for (int mt = 0; mt < MT; mt++) {
        #pragma unroll
        for (int half = 0; half < 2; half++) {
            int row = mb + wm * (MT * 16) + mt * 16 + g + half * 8;
            int nat = row;
            if (MODE == 2) {
                int win = row >> 6, t = row & 63;
                int bI = win >> 8, wi = win & 255;
                int wr = wi >> 4,  wc = wi & 15;
                int rr = t  >> 3,  cc = t  & 7;
                nat = bI * 16384 + (wr * 8 + rr) * 128 + (wc * 8 + cc);
            }
            #pragma unroll
            for (int nt = 0; nt < 4; nt++) {
                int col = nb + wn * 32 + nt * 8 + tig * 2;
                float ox = acc[mt][nt][half * 2 + 0] + bias[col];
                float oy = acc[mt][nt][half * 2 + 1] + bias[col + 1];
                if (MODE == 2) {
                    float* C = (float*)Cv;
                    float2 s = *(const float2*)(add + (size_t)nat * DIM + col);
                    *(float2*)(C + (size_t)nat * DIM + col) = make_float2(ox + s.x, oy + s.y);
                } else if (MODE == 4) {
                    float* C = (float*)Cv;
                    float2 s = *(const float2*)(add + (size_t)row * N + col);
                    *(float2*)(C + (size_t)row * N + col) = make_float2(ox + s.x, oy + s.y);
                } else {
                    if (MODE == 3) {
                        ox = 0.5f * ox * (1.0f + erff(ox * 0.70710678118654752f));
                        oy = 0.5f * oy * (1.0f + erff(oy * 0.70710678118654752f));
                    }
                    __nv_bfloat16* C = (__nv_bfloat16*)Cv;
                    *(uint32_t*)(C + (size_t)row * N + col) = packbf(ox, oy);
                }
            }
        }
    }
}

// ---------------- Attention v4: all-bf16 fragments, shuffle-free PV -----------
// 128 threads = 4 warps per (window, head). Warp w owns q-rows 16w..16w+15 and
// all 256 KV. S (16x256) in fp32 accumulators; P->A-fragment is a pure pack
// (accumulator col layout {2t,2t+1} == bf16 A-fragment layout). No shuffles.
#define AQS 20      // u32 row stride for Q/K (16 data + 4 pad)
#define AVS 132     // u32 row stride for VT (128 data + 4 pad)
#define OFFK  1280
#define OFFVT 6400
#define OFFB  10624
#define ATTN_SMEM_BYTES ((10624 + 532) * 4)

__global__ __launch_bounds__(128) void attn_kernel(const float* __restrict__ rel_bias)
{
    extern __shared__ uint32_t sm4[];
    uint32_t* sQp  = sm4;            // 64 x 20
    uint32_t* sKp  = sm4 + OFFK;     // 256 x 20
    uint32_t* sVTp = sm4 + OFFVT;    // 32 x 132 : VT[d][j2] = {V[2j2][d], V[2j2+1][d]}
    float*    sB   = (float*)(sm4 + OFFB);   // 529

    int win = blockIdx.x, h = blockIdx.y;
    int tid = threadIdx.x;

    for (int r = tid; r < 529; r += 128) sB[r] = rel_bias[r * HEADS + h];

    const __nv_bfloat16* qb = g_q + (size_t)win * 64 * DIM + h * HD;
    #pragma unroll
    for (int it = 0; it < 2; it++) {
        int id = tid + it * 128;               // 0..255
        int row = id >> 2, c = id & 3;
        uint4 v = *(const uint4*)(qb + (size_t)row * DIM + c * 8);
        *(uint4*)&sQp[row * AQS + c * 4] = v;
    }
    const __nv_bfloat16* kb = g_kv + (size_t)win * 256 * (2 * DIM) + h * HD;
    const __nv_bfloat16* vb = kb + DIM;
    #pragma unroll
    for (int it = 0; it < 8; it++) {
        int id = tid + it * 128;               // 0..1023
        int row = id >> 2, c = id & 3;
        uint4 v = *(const uint4*)(kb + (size_t)row * (2 * DIM) + c * 8);
        *(uint4*)&sKp[row * AQS + c * 4] = v;
    }
    // V: thread = j2 (0..127), c = d-chunk
    #pragma unroll
    for (int c = 0; c < 4; c++) {
        int j2 = tid;
        uint4 r0 = *(const uint4*)(vb + (size_t)(2 * j2) * (2 * DIM) + c * 8);
        uint4 r1 = *(const uint4*)(vb + (size_t)(2 * j2 + 1) * (2 * DIM) + c * 8);
        const uint32_t* x = (const uint32_t*)&r0;
        const uint32_t* y = (const uint32_t*)&r1;
        #pragma unroll
        for (int dd = 0; dd < 4; dd++) {
            sVTp[(c * 8 + 2 * dd + 0) * AVS + j2] = __byte_perm(x[dd], y[dd], 0x5410);
            sVTp[(c * 8 + 2 * dd + 1) * AVS + j2] = __byte_perm(x[dd], y[dd], 0x7632);
        }
    }
    __syncthreads();

    int warp = tid >> 5, lane = tid & 31;
    int g = lane >> 2, tig = lane & 3;
    int r0 = warp * 16;

    // ---- QK: S = Q @ K^T (two k16 steps), 16x256 in registers
    float acc[32][4];
    #pragma unroll
    for (int nt = 0; nt < 32; nt++)
        #pragma unroll
        for (int i = 0; i < 4; i++) acc[nt][i] = 0.f;

    #pragma unroll
    for (int ks = 0; ks < 2; ks++) {
        const uint32_t* pq = sQp + (r0 + g) * AQS + 8 * ks + tig;
        uint32_t a[4];
        a[0] = pq[0];
        a[1] = pq[8 * AQS];
        a[2] = pq[4];
        a[3] = pq[8 * AQS + 4];
        #pragma unroll
        for (int nt = 0; nt < 32; nt++) {
            const uint32_t* pk = sKp + (nt * 8 + g) * AQS + 8 * ks + tig;
            uint32_t b[2] = {pk[0], pk[4]};
            mma_bf16(acc[nt], a, b);
        }
    }

    // ---- scale + bias: ridx = 23*(i>>3)+(i&7)+360 - 23*(j>>4)-(j&15)
    int i_lo = r0 + g, i_hi = i_lo + 8;
    int xlo = (i_lo >> 3) * 23 + (i_lo & 7) + 360;
    int xhi = (i_hi >> 3) * 23 + (i_hi & 7) + 360;
    #pragma unroll
    for (int nt = 0; nt < 32; nt++) {
        int j0 = nt * 8 + tig * 2, j1 = j0 + 1;
        int y0 = 23 * (j0 >> 4) + (j0 & 15);
        int y1 = 23 * (j1 >> 4) + (j1 & 15);
        acc[nt][0] = acc[nt][0] * SCALE + sB[xlo - y0];
        acc[nt][1] = acc[nt][1] * SCALE + sB[xlo - y1];
        acc[nt][2] = acc[nt][2] * SCALE + sB[xhi - y0];
        acc[nt][3] = acc[nt][3] * SCALE + sB[xhi - y1];
    }

    // ---- softmax, quad-shuffle reductions only
    float mlo = -1e30f, mhi = -1e30f;
    #pragma unroll
    for (int nt = 0; nt < 32; nt++) {
        mlo = fmaxf(mlo, fmaxf(acc[nt][0], acc[nt][1]));
        mhi = fmaxf(mhi, fmaxf(acc[nt][2], acc[nt][3]));
    }
    #pragma unroll
    for (int off = 1; off < 4; off <<= 1) {
        mlo = fmaxf(mlo, __shfl_xor_sync(0xffffffffu, mlo, off));
        mhi = fmaxf(mhi, __shfl_xor_sync(0xffffffffu, mhi, off));
    }
    float slo = 0.f, shi = 0.f;
    #pragma unroll
    for (int nt = 0; nt < 32; nt++) {
        acc[nt][0] = __expf(acc[nt][0] - mlo); slo += acc[nt][0];
        acc[nt][1] = __expf(acc[nt][1] - mlo); slo += acc[nt][1];
        acc[nt][2] = __expf(acc[nt][2] - mhi); shi += acc[nt][2];
        acc[nt][3] = __expf(acc[nt][3] - mhi); shi += acc[nt][3];
    }
    #pragma unroll
    for (int off = 1; off < 4; off <<= 1) {
        slo += __shfl_xor_sync(0xffffffffu, slo, off);
        shi += __shfl_xor_sync(0xffffffffu, shi, off);
    }
    float invlo = 1.0f / slo, invhi = 1.0f / shi;
    #pragma unroll
    for (int nt = 0; nt < 32; nt++) {
        acc[nt][0] *= invlo; acc[nt][1] *= invlo;
        acc[nt][2] *= invhi; acc[nt][3] *= invhi;
    }

    // ---- PV: O = P @ V. P accumulator IS the bf16 A-fragment (pack only).
    float o[4][4];
    #pragma unroll
    for (int nt = 0; nt < 4; nt++)
        #pragma unroll
        for (int i = 0; i < 4; i++) o[nt][i] = 0.f;

    #pragma unroll
    for (int kc = 0; kc < 16; kc++) {
        uint32_t a[4];
        a[0] = packbf(acc[2 * kc][0],     acc[2 * kc][1]);
        a[1] = packbf(acc[2 * kc][2],     acc[2 * kc][3]);
        a[2] = packbf(acc[2 * kc + 1][0], acc[2 * kc + 1][1]);
        a[3] = packbf(acc[2 * kc + 1][2], acc[2 * kc + 1][3]);
        #pragma unroll
        for (int nt = 0; nt < 4; nt++) {
            const uint32_t* pv = sVTp + (nt * 8 + g) * AVS + 8 * kc + tig;
            uint32_t b[2] = {pv[0], pv[4]};
            mma_bf16(o[nt], a, b);
        }
    }

    // ---- store O (bf16)
    __nv_bfloat16* ob = g_ao + (size_t)win * 64 * DIM + h * HD;
    #pragma unroll
    for (int nt = 0; nt < 4; nt++) {
        int col = nt * 8 + tig * 2;
        *(uint32_t*)(ob + (size_t)i_lo * DIM + col) = packbf(o[nt][0], o[nt][1]);
        *(uint32_t*)(ob + (size_t)i_hi * DIM + col) = packbf(o[nt][2], o[nt][3]);
    }
}

// ---------------- launch ----------------
extern "C" void kernel_launch(void* const* d_in, const int* in_sizes, int n_in,
                              void* d_out, int out_size)
{
    const float* x     = (const float*)d_in[0];
    const float* x2    = (const float*)d_in[1];
    const float* n1w   = (const float*)d_in[2];
    const float* n1b   = (const float*)d_in[3];
    const float* qkvw  = (const float*)d_in[4];
    const float* qkvb  = (const float*)d_in[5];
    const float* qkv2w = (const float*)d_in[6];
    const float* qkv2b = (const float*)d_in[7];
    const float* relb  = (const float*)d_in[8];
    const float* projw = (const float*)d_in[9];
    const float* projb = (const float*)d_in[10];
    const float* n2w   = (const float*)d_in[11];
    const float* n2b   = (const float*)d_in[12];
    const float* fc1w  = (const float*)d_in[13];
    const float* fc1b  = (const float*)d_in[14];
    const float* fc2w  = (const float*)d_in[15];
    const float* fc2b  = (const float*)d_in[16];
    float* out = (float*)d_out;

    __nv_bfloat16 *p_xn, *p_q, *p_kv, *p_ao, *p_ln2, *p_h;
    __nv_bfloat16 *p_wq, *p_wkv, *p_wp, *p_w1, *p_w2;
    float *p_x1;
    cudaGetSymbolAddress((void**)&p_xn,  g_xn);
    cudaGetSymbolAddress((void**)&p_q,   g_q);
    cudaGetSymbolAddress((void**)&p_kv,  g_kv);
    cudaGetSymbolAddress((void**)&p_ao,  g_ao);
    cudaGetSymbolAddress((void**)&p_x1,  g_x1);
    cudaGetSymbolAddress((void**)&p_ln2, g_ln2);
    cudaGetSymbolAddress((void**)&p_h,   g_h);
    cudaGetSymbolAddress((void**)&p_wq,  g_wq);
    cudaGetSymbolAddress((void**)&p_wkv, g_wkv);
    cudaGetSymbolAddress((void**)&p_wp,  g_wp);
    cudaGetSymbolAddress((void**)&p_w1,  g_w1);
    cudaGetSymbolAddress((void**)&p_w2,  g_w2);

    cudaFuncSetAttribute(attn_kernel, cudaFuncAttributeMaxDynamicSharedMemorySize, ATTN_SMEM_BYTES);
    cudaFuncSetAttribute(gemm_bf16<0, 192, 192, true, 128>, cudaFuncAttributeMaxDynamicSharedMemorySize, SM_BF128);
    cudaFuncSetAttribute(gemm_bf16<1, 384, 192, false, 256>, cudaFuncAttributeMaxDynamicSharedMemorySize, SM_FP256);
    cudaFuncSetAttribute(gemm_bf16<2, 192, 192, true, 128>, cudaFuncAttributeMaxDynamicSharedMemorySize, SM_BF128);
    cudaFuncSetAttribute(gemm_bf16<3, 768, 192, true, 128>, cudaFuncAttributeMaxDynamicSharedMemorySize, SM_BF128);
    cudaFuncSetAttribute(gemm_bf16<4, 192, 768, true, 128>, cudaFuncAttributeMaxDynamicSharedMemorySize, SM_BF128);

    // 0. all weights -> bf16 (one launch)
    cvt_all<<<432, 256>>>(qkvw, qkv2w, projw, fc1w, fc2w);

    // 1. LN1 + window partition (bf16 out)
    ln_kernel<0><<<NQTOK / 8, 256>>>(x, n1w, n1b, p_xn);
    // 2. q projection (BM=128, 3 CTAs/SM)
    gemm_bf16<0, 192, 192, true, 128><<<dim3(3, 512), 256, SM_BF128>>>(p_xn, p_wq, qkvb, p_q, nullptr);
    // 3. kv projection (R13 fused fp32 gather, BM=256; N-blocks fastest)
    gemm_bf16<1, 384, 192, false, 256><<<dim3(6, 1024), 256, SM_FP256>>>(x2, p_wkv, qkv2b, p_kv, nullptr);
    // 4. windowed cross attention
    attn_kernel<<<dim3(NWIN, HEADS), 128, ATTN_SMEM_BYTES>>>(relb);
    // 5. output projection + shortcut + window reverse (fp32 out)
    gemm_bf16<2, 192, 192, true, 128><<<dim3(3, 512), 256, SM_BF128>>>(p_ao, p_wp, projb, p_x1, x);
    // 6. LN2 (bf16 out)
    ln_kernel<1><<<NQTOK / 8, 256>>>(p_x1, n2w, n2b, p_ln2);
    // 7. fc1 + gelu
    gemm_bf16<3, 768, 192, true, 128><<<dim3(12, 512), 256, SM_BF128>>>(p_ln2, p_w1, fc1b, p_h, nullptr);
    // 8. fc2 + residual -> output (fp32)
    gemm_bf16<4, 192, 768, true, 128><<<dim3(3, 512), 256, SM_BF128>>>(p_h, p_w2, fc2b, out, p_x1);
}